// round 16
// baseline (speedup 1.0000x reference)
#include <cuda_runtime.h>
#include <cuda_bf16.h>
#include <math.h>

// ---------------- problem constants ----------------
#define BI    4
#define NN    1024
#define DIN   2048
#define SD    512
#define NH    8
#define NF    8
#define NC    20
#define NODES (BI*NN)            // 4096
#define WALLN 876                // 512 sim | 64 gat1 | 60 ref | 240 bbox
#define WALLP 896
#define COL_H1   512
#define COL_REF  576
#define COL_BBOX 636

// output layout (flattened tuple, f32)
#define OUT_NODE  80
#define OUT_REF   82000
#define OUT_BBOX  327760

// ---- sgemm smem: bf16 planes, 64B per 32-k row, XOR-swizzled chunks ----
#define ATB 8192                  // 128 rows * 64B
#define BTB 4096                  // 64 rows * 64B
#define BUFB (2*ATB + 2*BTB)      // Ah, Al, Bh, Bl = 24576
#define SGEMM_SMEM (3*BUFB)       // 73728, triple buffered
#define GBUFB (ATB + BTB)         // gram: hi only = 12288
#define GRAM_SMEM (3*GBUFB)       // 36864

// persistent sgemm: 296 workers = one full wave @ 2 CTA/SM
#define N_THREE 160               // 5 n-blocks (ref/bbox) x 32 m-blocks, 3-product
#define N_SINGLE 288              // 9 n-blocks x 32 m-blocks, 1-product
#define GRID_W 296

// gram triangle: tiles (mb in [0,8), nb in [0,16)) with nb <= 2*mb+1 -> 72
#define GRAM_TILES 72

// prep dispatch kernel block ranges
#define PREP_SPLIT 2048
#define PREP_PACK  1792
#define PREP_IOU   512
#define PREP_GRID  (PREP_SPLIT + PREP_PACK + PREP_IOU)

// gat1|gram dispatch
#define GG_GRAM (GRAM_TILES*BI)   // 288
#define GG_GAT1 (NODES/4)         // 1024 (4 dsts per 256-thr block)
#define GG_GRID (GG_GRAM + GG_GAT1)

// ---------------- scratch (static device memory; no allocs) ----------------
__device__ __nv_bfloat16 g_Ah[(size_t)NODES*DIN];
__device__ __nv_bfloat16 g_Al[(size_t)NODES*DIN];
__device__ __nv_bfloat16 g_Wh[(size_t)WALLP*DIN];
__device__ __nv_bfloat16 g_Wl[(size_t)WALLP*DIN];
__device__ float g_Call[(size_t)NODES*WALLP];
__device__ __nv_bfloat16 g_SFb[(size_t)NODES*SD];
__device__ float g_ES1[NODES*NH];
__device__ float g_ED1[NODES*NH];
__device__ unsigned g_M1[BI*NH];
__device__ float g_H2[NODES*NC];
__device__ float g_ES2[NODES];
__device__ float g_ED2[NODES];
__device__ unsigned g_M2[BI];
__device__ unsigned char g_simM[(size_t)BI*NN*NN];
__device__ int g_e1[(size_t)NODES*NN];
__device__ int g_e1cnt[NODES];
__device__ int g_cnt[32];          // per-m-block single-tile completion counters
__device__ int g_cnt2[BI];         // per-image gat2 block counters

// monotonic float<->uint encoding for atomicMax
__device__ __forceinline__ unsigned fenc(float f) {
    unsigned u = __float_as_uint(f);
    return (u & 0x80000000u) ? ~u : (u | 0x80000000u);
}
__device__ __forceinline__ float fdec(unsigned u) {
    u = (u & 0x80000000u) ? (u & 0x7fffffffu) : ~u;
    return __uint_as_float(u);
}
__device__ __forceinline__ float lrelu(float x) { return x > 0.f ? x : 0.2f * x; }

// k-permutation within each 16-group: fragment quads {k,k+1,k+8,k+9} contiguous
__device__ __forceinline__ int kperm(int r) {
    return ((r & 6) << 1) | (r & 1) | ((r & 8) >> 2);
}

#define MMA_BF16(c, a, b)                                                   \
    asm("mma.sync.aligned.m16n8k16.row.col.f32.bf16.bf16.f32 "              \
        "{%0,%1,%2,%3}, {%4,%5,%6,%7}, {%8,%9}, {%0,%1,%2,%3};"             \
        : "+f"((c)[0]), "+f"((c)[1]), "+f"((c)[2]), "+f"((c)[3])            \
        : "r"((a)[0]), "r"((a)[1]), "r"((a)[2]), "r"((a)[3]),               \
          "r"((b)[0]), "r"((b)[1]))

#define CP16(dst, src)                                                      \
    asm volatile("cp.async.cg.shared.global [%0], [%1], 16;"                \
                 :: "r"(dst), "l"(src))
#define CP_COMMIT() asm volatile("cp.async.commit_group;")
#define CP_WAIT1()  asm volatile("cp.async.wait_group 1;")
#define CP_WAIT0()  asm volatile("cp.async.wait_group 0;")

// ---------------- fused prep: splitA | pack | iou_csr ----------------
__global__ void prep_kernel(const float* __restrict__ A,
                            const float* __restrict__ simW, const float* __restrict__ gat1W,
                            const float* __restrict__ refW, const float* __restrict__ bboxW,
                            const float* __restrict__ boxes) {
    __shared__ float4 bx4[NN];
    __shared__ float tile[32][33];
    int b = blockIdx.x, t = threadIdx.x;

    if (b < PREP_SPLIT) {
        size_t idx = (size_t)b * 256 + t;
        const float4* s4 = (const float4*)(A + idx * 16);
        float v[16];
#pragma unroll
        for (int i = 0; i < 4; i++) {
            float4 q = s4[i];
            v[i*4+0] = q.x; v[i*4+1] = q.y; v[i*4+2] = q.z; v[i*4+3] = q.w;
        }
        __nv_bfloat16 hb[16], lb[16];
#pragma unroll
        for (int r = 0; r < 16; r++) {
            __nv_bfloat16 h = __float2bfloat16_rn(v[r]);
            __nv_bfloat16 l = __float2bfloat16_rn(v[r] - __bfloat162float(h));
            int j = kperm(r);
            hb[j] = h; lb[j] = l;
        }
        ((uint4*)(g_Ah + idx * 16))[0] = ((uint4*)hb)[0];
        ((uint4*)(g_Ah + idx * 16))[1] = ((uint4*)hb)[1];
        ((uint4*)(g_Al + idx * 16))[0] = ((uint4*)lb)[0];
        ((uint4*)(g_Al + idx * 16))[1] = ((uint4*)lb)[1];
        return;
    }
    if (b < PREP_SPLIT + PREP_PACK) {
        int pb = b - PREP_SPLIT;
        int nt = (pb % 28) * 32, kt = (pb / 28) * 32;
        int tx = t & 31, ty = t >> 5;
        if (pb == 0) {
            if (ty == 0) {
                if (tx < BI*NH) g_M1[tx] = 0u;
                if (tx < BI)    g_M2[tx] = 0u;
            }
            if (ty == 1 && tx < 32) g_cnt[tx] = 0;
            if (ty == 2 && tx < BI) g_cnt2[tx] = 0;
        }
#pragma unroll
        for (int r = 0; r < 4; r++) {
            int k = kt + ty + r * 8;
            int n = nt + tx;
            float v = 0.f;
            if (n < COL_H1)        v = simW[(size_t)k*SD + n];
            else if (n < COL_REF)  v = gat1W[(size_t)k*64 + (n - COL_H1)];
            else if (n < COL_BBOX) { int jj = n - COL_REF;  int t3 = jj/NC; int c = jj%NC;
                                     v = refW[(size_t)t3*DIN*NC + (size_t)k*NC + c]; }
            else if (n < WALLN)    { int jj = n - COL_BBOX; int t3 = jj/80; int c = jj%80;
                                     v = bboxW[(size_t)t3*DIN*80 + (size_t)k*80 + c]; }
            tile[ty + r * 8][tx] = v;
        }
        __syncthreads();
#pragma unroll
        for (int r = 0; r < 4; r++) {
            int n = nt + ty + r * 8;
            int k = kt + tx;
            int kp = (k & ~15) | kperm(k & 15);
            float v = tile[tx][ty + r * 8];
            __nv_bfloat16 h = __float2bfloat16_rn(v);
            g_Wh[(size_t)n*DIN + kp] = h;
            g_Wl[(size_t)n*DIN + kp] = __float2bfloat16_rn(v - __bfloat162float(h));
        }
        return;
    }
    {
        int ib = b - PREP_SPLIT - PREP_PACK;
        int img = ib >> 7, blk = ib & 127;
        const float4* bsrc = (const float4*)(boxes + (size_t)img * NN * 4);
        for (int i = t; i < NN; i += 256) bx4[i] = bsrc[i];
        __syncthreads();
        int warp = t >> 5, lane = t & 31;
        int d = blk * 8 + warp;
        int gd = img * NN + d;
        int* lst = g_e1 + (size_t)gd * NN;
        float4 Ab = bx4[d];
        float areaA = (Ab.z - Ab.x) * (Ab.w - Ab.y);
        int base = 0;
        for (int p = 0; p < 32; p++) {
            int s = p * 32 + lane;
            float4 Bb = bx4[s];
            float areaB = (Bb.z - Bb.x) * (Bb.w - Bb.y);
            float lx = fmaxf(Ab.x, Bb.x), ly = fmaxf(Ab.y, Bb.y);
            float rx = fminf(Ab.z, Bb.z), ry = fminf(Ab.w, Bb.w);
            float w = fmaxf(rx - lx, 0.f), hh = fmaxf(ry - ly, 0.f);
            float inter = w * hh;
            float iou = inter / (areaA + areaB - inter + 1e-9f);
            bool flag = (iou >= 0.4f) || (s == d);
            unsigned m = __ballot_sync(0xffffffffu, flag);
            if (flag) lst[base + __popc(m & ((1u << lane) - 1u))] = s;
            base += __popc(m);
        }
        if (lane == 0) g_e1cnt[gd] = base;
    }
}

// direct-to-output store for ref/bbox columns (col >= COL_REF)
__device__ __forceinline__ void store_out(float v, int row, int col, float* __restrict__ out,
                                          const float* __restrict__ refb,
                                          const float* __restrict__ bboxb) {
    if (col >= WALLN) return;
    if (col < COL_BBOX) {
        int jj = col - COL_REF;
        int k = jj / NC, c = jj - k * NC;
        out[OUT_REF + (size_t)k * (NODES * NC) + (size_t)row * NC + c] = v + refb[k * NC + c];
    } else {
        int jj = col - COL_BBOX;
        int k = jj / 80, c = jj - k * 80;
        out[OUT_BBOX + (size_t)k * (NODES * 80) + (size_t)row * 80 + c] = v + bboxb[k * 80 + c];
    }
}

// Persistent merged GEMM + in-kernel normalization (last-single-tile pattern).
__global__ __launch_bounds__(256, 2) void sgemm_tc_pipe(float* __restrict__ out,
                                                        const float* __restrict__ refb,
                                                        const float* __restrict__ bboxb,
                                                        const float* __restrict__ simb,
                                                        const float* __restrict__ asrc1,
                                                        const float* __restrict__ adst1) {
    extern __shared__ char smem[];
    const int t = threadIdx.x;
    const int lane = t & 31, w = t >> 5;
    const int wm = w >> 1, wn = w & 1;
    const int q = lane & 3, g = lane >> 2;

    auto run_tile = [&](int bx, int by) {
        const int m0 = by * 128;
        const int n0 = bx * 64;
        const bool three = (n0 >= COL_REF);
        const char* AhB = (const char*)(g_Ah + (size_t)m0 * DIN);
        const char* AlB = (const char*)(g_Al + (size_t)m0 * DIN);
        const char* BhB = (const char*)(g_Wh + (size_t)n0 * DIN);
        const char* BlB = (const char*)(g_Wl + (size_t)n0 * DIN);

        __syncthreads();   // protect buffer reuse across tiles

        float acc[2][4][4];
#pragma unroll
        for (int mt = 0; mt < 2; mt++)
#pragma unroll
            for (int nt = 0; nt < 4; nt++)
#pragma unroll
                for (int i = 0; i < 4; i++) acc[mt][nt][i] = 0.f;

        auto stage = [&](int kt, int buf) {
            char* base = smem + buf * BUFB;
            size_t koff = (size_t)kt * 64;
#pragma unroll
            for (int j = 0; j < 2; j++) {
                int idx = t + j * 256;
                int m = idx >> 2, c = idx & 3;
                int doff = m * 64 + ((c ^ (m & 3)) << 4);
                CP16((unsigned)__cvta_generic_to_shared(base + doff),
                     AhB + (size_t)m * DIN * 2 + koff + c * 16);
            }
            {
                int n = t >> 2, c = t & 3;
                int doff = n * 64 + ((c ^ (n & 3)) << 4);
                CP16((unsigned)__cvta_generic_to_shared(base + 2*ATB + doff),
                     BhB + (size_t)n * DIN * 2 + koff + c * 16);
            }
            if (three) {
#pragma unroll
                for (int j = 0; j < 2; j++) {
                    int idx = t + j * 256;
                    int m = idx >> 2, c = idx & 3;
                    int doff = m * 64 + ((c ^ (m & 3)) << 4);
                    CP16((unsigned)__cvta_generic_to_shared(base + ATB + doff),
                         AlB + (size_t)m * DIN * 2 + koff + c * 16);
                }
                {
                    int n = t >> 2, c = t & 3;
                    int doff = n * 64 + ((c ^ (n & 3)) << 4);
                    CP16((unsigned)__cvta_generic_to_shared(base + 2*ATB + BTB + doff),
                         BlB + (size_t)n * DIN * 2 + koff + c * 16);
                }
            }
        };

        const int T = DIN / 32;
        stage(0, 0); CP_COMMIT();
        stage(1, 1); CP_COMMIT();
        for (int kt = 0; kt < T; kt++) {
            int cur = kt % 3;
            if (kt == T - 1) { CP_WAIT0(); } else { CP_WAIT1(); }
            __syncthreads();
            const char* AhS = smem + cur * BUFB;
            const char* AlS = AhS + ATB;
            const char* BhS = AhS + 2*ATB;
            const char* BlS = BhS + BTB;
#pragma unroll
            for (int s = 0; s < 2; s++) {
                unsigned ah[2][4], al[2][4], bh[4][2], bl[4][2];
                int sc = (s << 1) | (q >> 1);
                int hb = (q & 1) << 3;
#pragma unroll
                for (int mt = 0; mt < 2; mt++) {
                    int r0 = wm*32 + mt*16 + g;
                    int off0 = r0 * 64 + ((sc ^ (r0 & 3)) << 4) + hb;
                    uint2 v0 = *(const uint2*)(AhS + off0);
                    uint2 v1 = *(const uint2*)(AhS + off0 + 512);
                    ah[mt][0] = v0.x; ah[mt][1] = v1.x; ah[mt][2] = v0.y; ah[mt][3] = v1.y;
                    if (three) {
                        uint2 u0 = *(const uint2*)(AlS + off0);
                        uint2 u1 = *(const uint2*)(AlS + off0 + 512);
                        al[mt][0] = u0.x; al[mt][1] = u1.x; al[mt][2] = u0.y; al[mt][3] = u1.y;
                    }
                }
#pragma unroll
                for (int nt = 0; nt < 4; nt++) {
                    int n = wn*32 + nt*8 + g;
                    int off = n * 64 + ((sc ^ (n & 3)) << 4) + hb;
                    uint2 vb = *(const uint2*)(BhS + off);
                    bh[nt][0] = vb.x; bh[nt][1] = vb.y;
                    if (three) {
                        uint2 ub = *(const uint2*)(BlS + off);
                        bl[nt][0] = ub.x; bl[nt][1] = ub.y;
                    }
                }
#pragma unroll
                for (int mt = 0; mt < 2; mt++)
#pragma unroll
                    for (int nt = 0; nt < 4; nt++) {
                        MMA_BF16(acc[mt][nt], ah[mt], bh[nt]);
                        if (three) {
                            MMA_BF16(acc[mt][nt], al[mt], bh[nt]);
                            MMA_BF16(acc[mt][nt], ah[mt], bl[nt]);
                        }
                    }
            }
            if (kt + 2 < T) { stage(kt + 2, (kt + 2) % 3); CP_COMMIT(); }
        }

        if (n0 >= COL_REF) {
#pragma unroll
            for (int mt = 0; mt < 2; mt++)
#pragma unroll
                for (int nt = 0; nt < 4; nt++) {
                    int row = m0 + wm*32 + mt*16 + g;
                    int col = n0 + wn*32 + nt*8 + (q << 1);
                    store_out(acc[mt][nt][0], row,     col,     out, refb, bboxb);
                    store_out(acc[mt][nt][1], row,     col + 1, out, refb, bboxb);
                    store_out(acc[mt][nt][2], row + 8, col,     out, refb, bboxb);
                    store_out(acc[mt][nt][3], row + 8, col + 1, out, refb, bboxb);
                }
        } else {
#pragma unroll
            for (int mt = 0; mt < 2; mt++)
#pragma unroll
                for (int nt = 0; nt < 4; nt++) {
                    int row = m0 + wm*32 + mt*16 + g;
                    int col = n0 + wn*32 + nt*8 + (q << 1);
                    *(float2*)&g_Call[(size_t)row * WALLP + col] =
                        make_float2(acc[mt][nt][0], acc[mt][nt][1]);
                    *(float2*)&g_Call[(size_t)(row + 8) * WALLP + col] =
                        make_float2(acc[mt][nt][2], acc[mt][nt][3]);
                }
            // last-tile-of-m-block does the normalization + edge scalars
            __shared__ int s_old;
            __syncthreads();
            if (t == 0) { __threadfence(); s_old = atomicAdd(&g_cnt[by], 1); }
            __syncthreads();
            if (s_old == 8) {
                __threadfence();
                for (int rr = 0; rr < 16; rr++) {
                    int row = m0 + w * 16 + rr;
                    int img = row >> 10;
                    const float* rowp = g_Call + (size_t)row * WALLP;
                    if (lane < NH) {
                        float es = 0.f, edv = 0.f;
#pragma unroll
                        for (int f = 0; f < NF; f++) {
                            float v = rowp[COL_H1 + lane * NF + f];
                            es  = fmaf(v, asrc1[lane * NF + f], es);
                            edv = fmaf(v, adst1[lane * NF + f], edv);
                        }
                        g_ES1[row * NH + lane] = es;
                        g_ED1[row * NH + lane] = edv;
                        atomicMax(&g_M1[img * NH + lane], fenc(es));
                    }
                    float ss = 0.f;
                    for (int c = lane; c < SD; c += 32) {
                        float v = rowp[c] + simb[c]; ss += v * v;
                    }
#pragma unroll
                    for (int off = 16; off > 0; off >>= 1)
                        ss += __shfl_xor_sync(0xffffffffu, ss, off);
                    float inv = 1.f / (sqrtf(ss) + 1e-9f);
                    for (int c = lane; c < SD; c += 32) {
                        float v = (rowp[c] + simb[c]) * inv;
                        int cp = (c & ~15) | kperm(c & 15);
                        g_SFb[(size_t)row * SD + cp] = __float2bfloat16_rn(v);
                    }
                }
            }
        }
    };

    int b = blockIdx.x;
    if (b < N_THREE) {
        run_tile(9 + b % 5, b / 5);
    } else {
        for (int s = b - N_THREE; s < N_SINGLE; s += (GRID_W - N_THREE))
            run_tile(s % 9, s / 9);
    }
}

// ---------------- fused gat1 | gram dispatch ----------------
__global__ __launch_bounds__(256) void gat1_gram_kernel(
    const float* __restrict__ b1, const float* __restrict__ W2,
    const float* __restrict__ asrc2, const float* __restrict__ adst2) {
    extern __shared__ char smem[];
    const int t = threadIdx.x;
    int b = blockIdx.x;

    if (b >= GG_GRAM) {
        __shared__ float sh_n1[4][64];
        __shared__ float sh_h2[4][NC];
        int sub = t >> 6, c = t & 63;
        int gd = (b - GG_GRAM) * 4 + sub;
        int img = gd >> 10;
        int h = c >> 3;
        float ed = g_ED1[gd * NH + h];
        float shift = lrelu(fdec(g_M1[img * NH + h]) + ed);
        int cnt = g_e1cnt[gd];
        const int* lst = g_e1 + (size_t)gd * NN;
        float acc = 0.f, den = 0.f;
        for (int e = 0; e < cnt; e++) {
            int s = lst[e];
            int gs = (img << 10) + s;
            float es = g_ES1[gs * NH + h];
            float w = __expf(lrelu(es + ed) - shift);
            den += w;
            acc = fmaf(w, g_Call[(size_t)gs * WALLP + COL_H1 + c], acc);
        }
        float v = acc / den + b1[c];
        sh_n1[sub][c] = v > 0.f ? v : expm1f(v);
        __syncthreads();
        if (c < NC) {
            float a = 0.f;
#pragma unroll
            for (int k = 0; k < 64; k++) a = fmaf(sh_n1[sub][k], W2[k * NC + c], a);
            g_H2[gd * NC + c] = a;
            sh_h2[sub][c] = a;
        }
        __syncthreads();
        if (c == 0) {
            float es = 0.f, ed2 = 0.f;
#pragma unroll
            for (int cc = 0; cc < NC; cc++) {
                es  = fmaf(sh_h2[sub][cc], asrc2[cc], es);
                ed2 = fmaf(sh_h2[sub][cc], adst2[cc], ed2);
            }
            g_ES2[gd] = es;
            g_ED2[gd] = ed2;
            atomicMax(&g_M2[img], fenc(es));
        }
        return;
    }

    const int img = b / GRAM_TILES;
    int rem = b % GRAM_TILES;
    const char* SF = (const char*)(g_SFb + (size_t)img * NN * SD);
    const int lane = t & 31, w = t >> 5;
    const int wm = w >> 1, wn = w & 1;
    int mb = 0;
    while (rem >= 2 * mb + 2) { rem -= 2 * mb + 2; mb++; }
    const int m0 = mb * 128;
    const int n0 = rem * 64;

    const char* Abase = SF + (size_t)m0 * SD * 2;
    const char* Bbase = SF + (size_t)n0 * SD * 2;

    float acc[2][4][4];
#pragma unroll
    for (int mt = 0; mt < 2; mt++)
#pragma unroll
        for (int nt = 0; nt < 4; nt++)
#pragma unroll
            for (int i = 0; i < 4; i++) acc[mt][nt][i] = 0.f;

    auto stage = [&](int kt, int buf) {
        char* base = smem + buf * GBUFB;
        size_t koff = (size_t)kt * 64;
#pragma unroll
        for (int j = 0; j < 2; j++) {
            int idx = t + j * 256;
            int m = idx >> 2, c = idx & 3;
            int doff = m * 64 + ((c ^ (m & 3)) << 4);
            CP16((unsigned)__cvta_generic_to_shared(base + doff),
                 Abase + (size_t)m * SD * 2 + koff + c * 16);
        }
        {
            int n = t >> 2, c = t & 3;
            int doff = n * 64 + ((c ^ (n & 3)) << 4);
            CP16((unsigned)__cvta_generic_to_shared(base + ATB + doff),
                 Bbase + (size_t)n * SD * 2 + koff + c * 16);
        }
    };

    const int T = SD / 32;
    stage(0, 0); CP_COMMIT();
    stage(1, 1); CP_COMMIT();
    const int q = lane & 3, g = lane >> 2;
    for (int kt = 0; kt < T; kt++) {
        int cur = kt % 3;
        if (kt == T - 1) { CP_WAIT0(); } else { CP_WAIT1(); }
        __syncthreads();
        const char* AhS = smem + cur * GBUFB;
        const char* BhS = AhS + ATB;
#pragma unroll
        for (int s = 0; s < 2; s++) {
            unsigned ah[2][4], bh[4][2];
            int sc = (s << 1) | (q >> 1);
            int hb = (q & 1) << 3;
#pragma unroll
            for (int mt = 0; mt < 2; mt++) {
                int r0 = wm*32 + mt*16 + g;
                int off0 = r0 * 64 + ((sc ^ (r0 & 3)) << 4) + hb;
                uint2 v0 = *(const uint2*)(AhS + off0);
                uint2 v1 = *(const uint2*)(AhS + off0 + 512);
                ah[mt][0] = v0.x; ah[mt][1] = v1.x; ah[mt][2] = v0.y; ah[mt][3] = v1.y;
            }
#pragma unroll
            for (int nt = 0; nt < 4; nt++) {
                int n = wn*32 + nt*8 + g;
                int off = n * 64 + ((sc ^ (n & 3)) << 4) + hb;
                uint2 vb = *(const uint2*)(BhS + off);
                bh[nt][0] = vb.x; bh[nt][1] = vb.y;
            }
#pragma unroll
            for (int mt = 0; mt < 2; mt++)
#pragma unroll
                for (int nt = 0; nt < 4; nt++)
                    MMA_BF16(acc[mt][nt], ah[mt], bh[nt]);
        }
        if (kt + 2 < T) { stage(kt + 2, (kt + 2) % 3); CP_COMMIT(); }
    }
    unsigned char* M = g_simM + (size_t)img * NN * NN;
#pragma unroll
    for (int mt = 0; mt < 2; mt++)
#pragma unroll
        for (int nt = 0; nt < 4; nt++) {
            int s0 = m0 + wm*32 + mt*16 + g;
            int d0 = n0 + wn*32 + nt*8 + (q << 1);
            unsigned char v00 = (unsigned char)((acc[mt][nt][0] >= 0.4f) || (s0 == d0));
            unsigned char v01 = (unsigned char)((acc[mt][nt][1] >= 0.4f) || (s0 == d0+1));
            unsigned char v10 = (unsigned char)((acc[mt][nt][2] >= 0.4f) || (s0+8 == d0));
            unsigned char v11 = (unsigned char)((acc[mt][nt][3] >= 0.4f) || (s0+8 == d0+1));
            M[(size_t)d0 * NN + s0]       = v00;
            M[(size_t)(d0+1) * NN + s0]   = v01;
            M[(size_t)d0 * NN + s0+8]     = v10;
            M[(size_t)(d0+1) * NN + s0+8] = v11;
            M[(size_t)s0 * NN + d0]       = v00;
            M[(size_t)s0 * NN + d0+1]     = v01;
            M[(size_t)(s0+8) * NN + d0]   = v10;
            M[(size_t)(s0+8) * NN + d0+1] = v11;
        }
}

// FUSED GAT2 aggregation + node head + softmax + graph mean (last block/image)
__global__ void gat2_node_kernel(const float* __restrict__ b2,
                                 const float* __restrict__ nW,
                                 const float* __restrict__ nb,
                                 float* __restrict__ out) {
    __shared__ float sh_x[8][NC];
    __shared__ int s_last;
    int img = blockIdx.y, tid = threadIdx.x;
    int warp = tid >> 5, lane = tid & 31;
    int d = blockIdx.x * 8 + warp;
    int gd = img * NN + d;
    const unsigned char* M = g_simM + (size_t)img * NN * NN + (size_t)d * NN;
    float ed = g_ED2[gd];
    float shift = lrelu(fdec(g_M2[img]) + ed);
    float acc = 0.f, den = 0.f;
    for (int p = 0; p < 32; p++) {
        bool f = M[p * 32 + lane] != 0;
        unsigned bits = __ballot_sync(0xffffffffu, f);
        while (bits) {
            int b = __ffs(bits) - 1;
            bits &= bits - 1;
            int gs = (img << 10) + p * 32 + b;
            float w = __expf(lrelu(g_ES2[gs] + ed) - shift);
            den += w;
            if (lane < NC) acc = fmaf(w, g_H2[gs * NC + lane], acc);
        }
    }
    if (lane < NC) sh_x[warp][lane] = acc / den + b2[lane];
    __syncwarp();
    float a = -1e30f;
    if (lane < NC) {
        a = nb[lane];
#pragma unroll
        for (int cc = 0; cc < NC; cc++) a = fmaf(sh_x[warp][cc], nW[cc * NC + lane], a);
    }
    float m = a;
#pragma unroll
    for (int off = 16; off > 0; off >>= 1) m = fmaxf(m, __shfl_xor_sync(0xffffffffu, m, off));
    float e = (lane < NC) ? __expf(a - m) : 0.f;
    float s = e;
#pragma unroll
    for (int off = 16; off > 0; off >>= 1) s += __shfl_xor_sync(0xffffffffu, s, off);
    if (lane < NC) out[OUT_NODE + (size_t)gd * NC + lane] = e / s;

    // graph mean: last block of this image reduces all node scores
    __syncthreads();
    if (tid == 0) { __threadfence(); s_last = atomicAdd(&g_cnt2[img], 1); }
    __syncthreads();
    if (s_last == NN / 8 - 1) {
        __threadfence();
        for (int c = warp; c < NC; c += 8) {
            float gs = 0.f;
            for (int node = lane; node < NN; node += 32)
                gs += out[OUT_NODE + (size_t)(img * NN + node) * NC + c];
#pragma unroll
            for (int off = 16; off > 0; off >>= 1)
                gs += __shfl_xor_sync(0xffffffffu, gs, off);
            if (lane == 0) out[img * NC + c] = gs * (1.f / (float)NN);
        }
    }
}

// ---------------- launch ----------------
extern "C" void kernel_launch(void* const* d_in, const int* in_sizes, int n_in,
                              void* d_out, int out_size) {
    const float* x1     = (const float*)d_in[0];
    const float* boxes  = (const float*)d_in[1];
    const float* simW   = (const float*)d_in[2];
    const float* simb   = (const float*)d_in[3];
    const float* gat1W  = (const float*)d_in[4];
    const float* asrc1  = (const float*)d_in[5];
    const float* adst1  = (const float*)d_in[6];
    const float* b1     = (const float*)d_in[7];
    const float* gat2W  = (const float*)d_in[8];
    const float* asrc2  = (const float*)d_in[9];
    const float* adst2  = (const float*)d_in[10];
    const float* b2     = (const float*)d_in[11];
    const float* nodeW  = (const float*)d_in[12];
    const float* nodeb  = (const float*)d_in[13];
    const float* refW   = (const float*)d_in[14];
    const float* refb   = (const float*)d_in[15];
    const float* bboxW  = (const float*)d_in[16];
    const float* bboxb  = (const float*)d_in[17];
    float* out = (float*)d_out;

    cudaFuncSetAttribute(sgemm_tc_pipe,    cudaFuncAttributeMaxDynamicSharedMemorySize, SGEMM_SMEM);
    cudaFuncSetAttribute(gat1_gram_kernel, cudaFuncAttributeMaxDynamicSharedMemorySize, GRAM_SMEM);

    prep_kernel<<<PREP_GRID, 256>>>(x1, simW, gat1W, refW, bboxW, boxes);
    sgemm_tc_pipe<<<GRID_W, 256, SGEMM_SMEM>>>(out, refb, bboxb, simb, asrc1, adst1);
    gat1_gram_kernel<<<GG_GRID, 256, GRAM_SMEM>>>(b1, gat2W, asrc2, adst2);
    gat2_node_kernel<<<dim3(NN / 8, BI), 256>>>(b2, nodeW, nodeb, out);
}

// round 17
// speedup vs baseline: 1.6557x; 1.6557x over previous
#include <cuda_runtime.h>
#include <cuda_bf16.h>
#include <math.h>

// ---------------- problem constants ----------------
#define BI    4
#define NN    1024
#define DIN   2048
#define SD    512
#define NH    8
#define NF    8
#define NC    20
#define NODES (BI*NN)            // 4096
#define WALLN 876                // 512 sim | 64 gat1 | 60 ref | 240 bbox
#define WALLP 896
#define COL_H1   512
#define COL_REF  576
#define COL_BBOX 636

// output layout (flattened tuple, f32)
#define OUT_NODE  80
#define OUT_REF   82000
#define OUT_BBOX  327760

// ---- sgemm smem: bf16 planes, 64B per 32-k row, XOR-swizzled chunks ----
#define ATB 8192                  // 128 rows * 64B
#define BTB 4096                  // 64 rows * 64B
#define BUFB (2*ATB + 2*BTB)      // Ah, Al, Bh, Bl = 24576
#define SGEMM_SMEM (3*BUFB)       // 73728, triple buffered
#define GBUFB (ATB + BTB)         // gram: hi only = 12288
#define GRAM_SMEM (3*GBUFB)       // 36864

// persistent sgemm: 296 workers = one full wave @ 2 CTA/SM
#define N_THREE 160               // 5 n-blocks (ref/bbox) x 32 m-blocks, 3-product
#define N_SINGLE 288              // 9 n-blocks x 32 m-blocks, 1-product
#define GRID_W 296

// gram triangle: tiles (mb in [0,8), nb in [0,16)) with nb <= 2*mb+1 -> 72
#define GRAM_TILES 72

// prep dispatch kernel block ranges
#define PREP_SPLIT 2048
#define PREP_PACK  1792
#define PREP_IOU   512
#define PREP_GRID  (PREP_SPLIT + PREP_PACK + PREP_IOU)

// gat1|gram dispatch
#define GG_GRAM (GRAM_TILES*BI)   // 288
#define GG_GAT1 (NODES/4)         // 1024 (4 dsts per 256-thr block)
#define GG_GRID (GG_GRAM + GG_GAT1)

// ---------------- scratch (static device memory; no allocs) ----------------
__device__ __nv_bfloat16 g_Ah[(size_t)NODES*DIN];
__device__ __nv_bfloat16 g_Al[(size_t)NODES*DIN];
__device__ __nv_bfloat16 g_Wh[(size_t)WALLP*DIN];
__device__ __nv_bfloat16 g_Wl[(size_t)WALLP*DIN];
__device__ float g_Call[(size_t)NODES*WALLP];
__device__ __nv_bfloat16 g_SFb[(size_t)NODES*SD];
__device__ float g_ES1[NODES*NH];
__device__ float g_ED1[NODES*NH];
__device__ unsigned g_M1[BI*NH];
__device__ float g_H2[NODES*NC];
__device__ float g_ES2[NODES];
__device__ float g_ED2[NODES];
__device__ unsigned g_M2[BI];
__device__ unsigned char g_simM[(size_t)BI*NN*NN];
__device__ int g_e1[(size_t)NODES*NN];
__device__ int g_e1cnt[NODES];

// monotonic float<->uint encoding for atomicMax
__device__ __forceinline__ unsigned fenc(float f) {
    unsigned u = __float_as_uint(f);
    return (u & 0x80000000u) ? ~u : (u | 0x80000000u);
}
__device__ __forceinline__ float fdec(unsigned u) {
    u = (u & 0x80000000u) ? (u & 0x7fffffffu) : ~u;
    return __uint_as_float(u);
}
__device__ __forceinline__ float lrelu(float x) { return x > 0.f ? x : 0.2f * x; }

// k-permutation within each 16-group: fragment quads {k,k+1,k+8,k+9} contiguous
__device__ __forceinline__ int kperm(int r) {
    return ((r & 6) << 1) | (r & 1) | ((r & 8) >> 2);
}

#define MMA_BF16(c, a, b)                                                   \
    asm("mma.sync.aligned.m16n8k16.row.col.f32.bf16.bf16.f32 "              \
        "{%0,%1,%2,%3}, {%4,%5,%6,%7}, {%8,%9}, {%0,%1,%2,%3};"             \
        : "+f"((c)[0]), "+f"((c)[1]), "+f"((c)[2]), "+f"((c)[3])            \
        : "r"((a)[0]), "r"((a)[1]), "r"((a)[2]), "r"((a)[3]),               \
          "r"((b)[0]), "r"((b)[1]))

#define CP16(dst, src)                                                      \
    asm volatile("cp.async.cg.shared.global [%0], [%1], 16;"                \
                 :: "r"(dst), "l"(src))
#define CP_COMMIT() asm volatile("cp.async.commit_group;")
#define CP_WAIT1()  asm volatile("cp.async.wait_group 1;")
#define CP_WAIT0()  asm volatile("cp.async.wait_group 0;")

// ---------------- fused prep: splitA | pack | iou_csr ----------------
__global__ void prep_kernel(const float* __restrict__ A,
                            const float* __restrict__ simW, const float* __restrict__ gat1W,
                            const float* __restrict__ refW, const float* __restrict__ bboxW,
                            const float* __restrict__ boxes) {
    __shared__ float4 bx4[NN];
    __shared__ float tile[32][33];
    int b = blockIdx.x, t = threadIdx.x;

    if (b < PREP_SPLIT) {
        size_t idx = (size_t)b * 256 + t;
        const float4* s4 = (const float4*)(A + idx * 16);
        float v[16];
#pragma unroll
        for (int i = 0; i < 4; i++) {
            float4 q = s4[i];
            v[i*4+0] = q.x; v[i*4+1] = q.y; v[i*4+2] = q.z; v[i*4+3] = q.w;
        }
        __nv_bfloat16 hb[16], lb[16];
#pragma unroll
        for (int r = 0; r < 16; r++) {
            __nv_bfloat16 h = __float2bfloat16_rn(v[r]);
            __nv_bfloat16 l = __float2bfloat16_rn(v[r] - __bfloat162float(h));
            int j = kperm(r);
            hb[j] = h; lb[j] = l;
        }
        ((uint4*)(g_Ah + idx * 16))[0] = ((uint4*)hb)[0];
        ((uint4*)(g_Ah + idx * 16))[1] = ((uint4*)hb)[1];
        ((uint4*)(g_Al + idx * 16))[0] = ((uint4*)lb)[0];
        ((uint4*)(g_Al + idx * 16))[1] = ((uint4*)lb)[1];
        return;
    }
    if (b < PREP_SPLIT + PREP_PACK) {
        int pb = b - PREP_SPLIT;
        int nt = (pb % 28) * 32, kt = (pb / 28) * 32;
        int tx = t & 31, ty = t >> 5;
        if (pb == 0 && ty == 0) {
            if (tx < BI*NH) g_M1[tx] = 0u;
            if (tx < BI)    g_M2[tx] = 0u;
        }
#pragma unroll
        for (int r = 0; r < 4; r++) {
            int k = kt + ty + r * 8;
            int n = nt + tx;
            float v = 0.f;
            if (n < COL_H1)        v = simW[(size_t)k*SD + n];
            else if (n < COL_REF)  v = gat1W[(size_t)k*64 + (n - COL_H1)];
            else if (n < COL_BBOX) { int jj = n - COL_REF;  int t3 = jj/NC; int c = jj%NC;
                                     v = refW[(size_t)t3*DIN*NC + (size_t)k*NC + c]; }
            else if (n < WALLN)    { int jj = n - COL_BBOX; int t3 = jj/80; int c = jj%80;
                                     v = bboxW[(size_t)t3*DIN*80 + (size_t)k*80 + c]; }
            tile[ty + r * 8][tx] = v;
        }
        __syncthreads();
#pragma unroll
        for (int r = 0; r < 4; r++) {
            int n = nt + ty + r * 8;
            int k = kt + tx;
            int kp = (k & ~15) | kperm(k & 15);
            float v = tile[tx][ty + r * 8];
            __nv_bfloat16 h = __float2bfloat16_rn(v);
            g_Wh[(size_t)n*DIN + kp] = h;
            g_Wl[(size_t)n*DIN + kp] = __float2bfloat16_rn(v - __bfloat162float(h));
        }
        return;
    }
    {
        int ib = b - PREP_SPLIT - PREP_PACK;
        int img = ib >> 7, blk = ib & 127;
        const float4* bsrc = (const float4*)(boxes + (size_t)img * NN * 4);
        for (int i = t; i < NN; i += 256) bx4[i] = bsrc[i];
        __syncthreads();
        int warp = t >> 5, lane = t & 31;
        int d = blk * 8 + warp;
        int gd = img * NN + d;
        int* lst = g_e1 + (size_t)gd * NN;
        float4 Ab = bx4[d];
        float areaA = (Ab.z - Ab.x) * (Ab.w - Ab.y);
        int base = 0;
        for (int p = 0; p < 32; p++) {
            int s = p * 32 + lane;
            float4 Bb = bx4[s];
            float areaB = (Bb.z - Bb.x) * (Bb.w - Bb.y);
            float lx = fmaxf(Ab.x, Bb.x), ly = fmaxf(Ab.y, Bb.y);
            float rx = fminf(Ab.z, Bb.z), ry = fminf(Ab.w, Bb.w);
            float w = fmaxf(rx - lx, 0.f), hh = fmaxf(ry - ly, 0.f);
            float inter = w * hh;
            float iou = inter / (areaA + areaB - inter + 1e-9f);
            bool flag = (iou >= 0.4f) || (s == d);
            unsigned m = __ballot_sync(0xffffffffu, flag);
            if (flag) lst[base + __popc(m & ((1u << lane) - 1u))] = s;
            base += __popc(m);
        }
        if (lane == 0) g_e1cnt[gd] = base;
    }
}

// direct-to-output store for ref/bbox columns (col >= COL_REF)
__device__ __forceinline__ void store_out(float v, int row, int col, float* __restrict__ out,
                                          const float* __restrict__ refb,
                                          const float* __restrict__ bboxb) {
    if (col >= WALLN) return;
    if (col < COL_BBOX) {
        int jj = col - COL_REF;
        int k = jj / NC, c = jj - k * NC;
        out[OUT_REF + (size_t)k * (NODES * NC) + (size_t)row * NC + c] = v + refb[k * NC + c];
    } else {
        int jj = col - COL_BBOX;
        int k = jj / 80, c = jj - k * 80;
        out[OUT_BBOX + (size_t)k * (NODES * 80) + (size_t)row * 80 + c] = v + bboxb[k * 80 + c];
    }
}

// Persistent merged GEMM (R15 winner, no in-kernel epilogue fusion).
__global__ __launch_bounds__(256, 2) void sgemm_tc_pipe(float* __restrict__ out,
                                                        const float* __restrict__ refb,
                                                        const float* __restrict__ bboxb) {
    extern __shared__ char smem[];
    const int t = threadIdx.x;
    const int lane = t & 31, w = t >> 5;
    const int wm = w >> 1, wn = w & 1;
    const int q = lane & 3, g = lane >> 2;

    auto run_tile = [&](int bx, int by) {
        const int m0 = by * 128;
        const int n0 = bx * 64;
        const bool three = (n0 >= COL_REF);
        const char* AhB = (const char*)(g_Ah + (size_t)m0 * DIN);
        const char* AlB = (const char*)(g_Al + (size_t)m0 * DIN);
        const char* BhB = (const char*)(g_Wh + (size_t)n0 * DIN);
        const char* BlB = (const char*)(g_Wl + (size_t)n0 * DIN);

        __syncthreads();   // protect buffer reuse across tiles

        float acc[2][4][4];
#pragma unroll
        for (int mt = 0; mt < 2; mt++)
#pragma unroll
            for (int nt = 0; nt < 4; nt++)
#pragma unroll
                for (int i = 0; i < 4; i++) acc[mt][nt][i] = 0.f;

        auto stage = [&](int kt, int buf) {
            char* base = smem + buf * BUFB;
            size_t koff = (size_t)kt * 64;
#pragma unroll
            for (int j = 0; j < 2; j++) {
                int idx = t + j * 256;
                int m = idx >> 2, c = idx & 3;
                int doff = m * 64 + ((c ^ (m & 3)) << 4);
                CP16((unsigned)__cvta_generic_to_shared(base + doff),
                     AhB + (size_t)m * DIN * 2 + koff + c * 16);
            }
            {
                int n = t >> 2, c = t & 3;
                int doff = n * 64 + ((c ^ (n & 3)) << 4);
                CP16((unsigned)__cvta_generic_to_shared(base + 2*ATB + doff),
                     BhB + (size_t)n * DIN * 2 + koff + c * 16);
            }
            if (three) {
#pragma unroll
                for (int j = 0; j < 2; j++) {
                    int idx = t + j * 256;
                    int m = idx >> 2, c = idx & 3;
                    int doff = m * 64 + ((c ^ (m & 3)) << 4);
                    CP16((unsigned)__cvta_generic_to_shared(base + ATB + doff),
                         AlB + (size_t)m * DIN * 2 + koff + c * 16);
                }
                {
                    int n = t >> 2, c = t & 3;
                    int doff = n * 64 + ((c ^ (n & 3)) << 4);
                    CP16((unsigned)__cvta_generic_to_shared(base + 2*ATB + BTB + doff),
                         BlB + (size_t)n * DIN * 2 + koff + c * 16);
                }
            }
        };

        const int T = DIN / 32;
        stage(0, 0); CP_COMMIT();
        stage(1, 1); CP_COMMIT();
        for (int kt = 0; kt < T; kt++) {
            int cur = kt % 3;
            if (kt == T - 1) { CP_WAIT0(); } else { CP_WAIT1(); }
            __syncthreads();
            const char* AhS = smem + cur * BUFB;
            const char* AlS = AhS + ATB;
            const char* BhS = AhS + 2*ATB;
            const char* BlS = BhS + BTB;
#pragma unroll
            for (int s = 0; s < 2; s++) {
                unsigned ah[2][4], al[2][4], bh[4][2], bl[4][2];
                int sc = (s << 1) | (q >> 1);
                int hb = (q & 1) << 3;
#pragma unroll
                for (int mt = 0; mt < 2; mt++) {
                    int r0 = wm*32 + mt*16 + g;
                    int off0 = r0 * 64 + ((sc ^ (r0 & 3)) << 4) + hb;
                    uint2 v0 = *(const uint2*)(AhS + off0);
                    uint2 v1 = *(const uint2*)(AhS + off0 + 512);
                    ah[mt][0] = v0.x; ah[mt][1] = v1.x; ah[mt][2] = v0.y; ah[mt][3] = v1.y;
                    if (three) {
                        uint2 u0 = *(const uint2*)(AlS + off0);
                        uint2 u1 = *(const uint2*)(AlS + off0 + 512);
                        al[mt][0] = u0.x; al[mt][1] = u1.x; al[mt][2] = u0.y; al[mt][3] = u1.y;
                    }
                }
#pragma unroll
                for (int nt = 0; nt < 4; nt++) {
                    int n = wn*32 + nt*8 + g;
                    int off = n * 64 + ((sc ^ (n & 3)) << 4) + hb;
                    uint2 vb = *(const uint2*)(BhS + off);
                    bh[nt][0] = vb.x; bh[nt][1] = vb.y;
                    if (three) {
                        uint2 ub = *(const uint2*)(BlS + off);
                        bl[nt][0] = ub.x; bl[nt][1] = ub.y;
                    }
                }
#pragma unroll
                for (int mt = 0; mt < 2; mt++)
#pragma unroll
                    for (int nt = 0; nt < 4; nt++) {
                        MMA_BF16(acc[mt][nt], ah[mt], bh[nt]);
                        if (three) {
                            MMA_BF16(acc[mt][nt], al[mt], bh[nt]);
                            MMA_BF16(acc[mt][nt], ah[mt], bl[nt]);
                        }
                    }
            }
            if (kt + 2 < T) { stage(kt + 2, (kt + 2) % 3); CP_COMMIT(); }
        }

        if (n0 >= COL_REF) {
#pragma unroll
            for (int mt = 0; mt < 2; mt++)
#pragma unroll
                for (int nt = 0; nt < 4; nt++) {
                    int row = m0 + wm*32 + mt*16 + g;
                    int col = n0 + wn*32 + nt*8 + (q << 1);
                    store_out(acc[mt][nt][0], row,     col,     out, refb, bboxb);
                    store_out(acc[mt][nt][1], row,     col + 1, out, refb, bboxb);
                    store_out(acc[mt][nt][2], row + 8, col,     out, refb, bboxb);
                    store_out(acc[mt][nt][3], row + 8, col + 1, out, refb, bboxb);
                }
        } else {
#pragma unroll
            for (int mt = 0; mt < 2; mt++)
#pragma unroll
                for (int nt = 0; nt < 4; nt++) {
                    int row = m0 + wm*32 + mt*16 + g;
                    int col = n0 + wn*32 + nt*8 + (q << 1);
                    *(float2*)&g_Call[(size_t)row * WALLP + col] =
                        make_float2(acc[mt][nt][0], acc[mt][nt][1]);
                    *(float2*)&g_Call[(size_t)(row + 8) * WALLP + col] =
                        make_float2(acc[mt][nt][2], acc[mt][nt][3]);
                }
        }
    };

    int b = blockIdx.x;
    if (b < N_THREE) {
        run_tile(9 + b % 5, b / 5);
    } else {
        for (int s = b - N_THREE; s < N_SINGLE; s += (GRID_W - N_THREE))
            run_tile(s % 9, s / 9);
    }
}

// fused: per-row L2 normalize (writes bf16 permuted SF) + gat1 edge scalars
__global__ void norm_edge_kernel(const float* __restrict__ simb,
                                 const float* __restrict__ asrc,
                                 const float* __restrict__ adst) {
    int r = blockIdx.x, tid = threadIdx.x;  // 128 threads
    const float* row = g_Call + (size_t)r * WALLP;
    if (tid < NH) {
        int img = r >> 10;
        float es = 0.f, ed = 0.f;
#pragma unroll
        for (int f = 0; f < NF; f++) {
            float v = row[COL_H1 + tid * NF + f];
            es = fmaf(v, asrc[tid * NF + f], es);
            ed = fmaf(v, adst[tid * NF + f], ed);
        }
        g_ES1[r * NH + tid] = es;
        g_ED1[r * NH + tid] = ed;
        atomicMax(&g_M1[img * NH + tid], fenc(es));
    }
    float ss = 0.f;
    for (int c = tid; c < SD; c += 128) { float v = row[c] + simb[c]; ss += v * v; }
#pragma unroll
    for (int off = 16; off > 0; off >>= 1) ss += __shfl_xor_sync(0xffffffffu, ss, off);
    __shared__ float red[4];
    if ((tid & 31) == 0) red[tid >> 5] = ss;
    __syncthreads();
    float tot = red[0] + red[1] + red[2] + red[3];
    float inv = 1.f / (sqrtf(tot) + 1e-9f);
    for (int c = tid; c < SD; c += 128) {
        float v = (row[c] + simb[c]) * inv;
        int cp = (c & ~15) | kperm(c & 15);
        g_SFb[(size_t)r * SD + cp] = __float2bfloat16_rn(v);
    }
}

// ---------------- fused gat1 | gram dispatch ----------------
__global__ __launch_bounds__(256) void gat1_gram_kernel(
    const float* __restrict__ b1, const float* __restrict__ W2,
    const float* __restrict__ asrc2, const float* __restrict__ adst2) {
    extern __shared__ char smem[];
    const int t = threadIdx.x;
    int b = blockIdx.x;

    if (b >= GG_GRAM) {
        // ---- gat1 branch: 4 dsts per block, 1-ahead software pipeline ----
        __shared__ float sh_n1[4][64];
        __shared__ float sh_h2[4][NC];
        int sub = t >> 6, c = t & 63;
        int gd = (b - GG_GRAM) * 4 + sub;
        int img = gd >> 10;
        int h = c >> 3;
        float ed = g_ED1[gd * NH + h];
        float shift = lrelu(fdec(g_M1[img * NH + h]) + ed);
        int cnt = g_e1cnt[gd];
        const int* lst = g_e1 + (size_t)gd * NN;
        float acc = 0.f, den = 0.f;
        // prologue: prefetch edge 0's data
        int gs_c = (img << 10) + lst[0];
        float es_c = g_ES1[gs_c * NH + h];
        float h1_c = g_Call[(size_t)gs_c * WALLP + COL_H1 + c];
        for (int e = 0; e < cnt; e++) {
            int gs_n = 0; float es_n = 0.f, h1_n = 0.f;
            if (e + 1 < cnt) {
                gs_n = (img << 10) + lst[e + 1];
                es_n = g_ES1[gs_n * NH + h];
                h1_n = g_Call[(size_t)gs_n * WALLP + COL_H1 + c];
            }
            float w = __expf(lrelu(es_c + ed) - shift);
            den += w;
            acc = fmaf(w, h1_c, acc);
            gs_c = gs_n; es_c = es_n; h1_c = h1_n;
        }
        float v = acc / den + b1[c];
        sh_n1[sub][c] = v > 0.f ? v : expm1f(v);
        __syncthreads();
        if (c < NC) {
            float a = 0.f;
#pragma unroll
            for (int k = 0; k < 64; k++) a = fmaf(sh_n1[sub][k], W2[k * NC + c], a);
            g_H2[gd * NC + c] = a;
            sh_h2[sub][c] = a;
        }
        __syncthreads();
        if (c == 0) {
            float es = 0.f, ed2 = 0.f;
#pragma unroll
            for (int cc = 0; cc < NC; cc++) {
                es  = fmaf(sh_h2[sub][cc], asrc2[cc], es);
                ed2 = fmaf(sh_h2[sub][cc], adst2[cc], ed2);
            }
            g_ES2[gd] = es;
            g_ED2[gd] = ed2;
            atomicMax(&g_M2[img], fenc(es));
        }
        return;
    }

    // ---- gram branch: triangular tiles, symmetric writes ----
    const int img = b / GRAM_TILES;
    int rem = b % GRAM_TILES;
    const char* SF = (const char*)(g_SFb + (size_t)img * NN * SD);
    const int lane = t & 31, w = t >> 5;
    const int wm = w >> 1, wn = w & 1;
    int mb = 0;
    while (rem >= 2 * mb + 2) { rem -= 2 * mb + 2; mb++; }
    const int m0 = mb * 128;
    const int n0 = rem * 64;

    const char* Abase = SF + (size_t)m0 * SD * 2;
    const char* Bbase = SF + (size_t)n0 * SD * 2;

    float acc[2][4][4];
#pragma unroll
    for (int mt = 0; mt < 2; mt++)
#pragma unroll
        for (int nt = 0; nt < 4; nt++)
#pragma unroll
            for (int i = 0; i < 4; i++) acc[mt][nt][i] = 0.f;

    auto stage = [&](int kt, int buf) {
        char* base = smem + buf * GBUFB;
        size_t koff = (size_t)kt * 64;
#pragma unroll
        for (int j = 0; j < 2; j++) {
            int idx = t + j * 256;
            int m = idx >> 2, c = idx & 3;
            int doff = m * 64 + ((c ^ (m & 3)) << 4);
            CP16((unsigned)__cvta_generic_to_shared(base + doff),
                 Abase + (size_t)m * SD * 2 + koff + c * 16);
        }
        {
            int n = t >> 2, c = t & 3;
            int doff = n * 64 + ((c ^ (n & 3)) << 4);
            CP16((unsigned)__cvta_generic_to_shared(base + ATB + doff),
                 Bbase + (size_t)n * SD * 2 + koff + c * 16);
        }
    };

    const int T = SD / 32;
    stage(0, 0); CP_COMMIT();
    stage(1, 1); CP_COMMIT();
    const int q = lane & 3, g = lane >> 2;
    for (int kt = 0; kt < T; kt++) {
        int cur = kt % 3;
        if (kt == T - 1) { CP_WAIT0(); } else { CP_WAIT1(); }
        __syncthreads();
        const char* AhS = smem + cur * GBUFB;
        const char* BhS = AhS + ATB;
#pragma unroll
        for (int s = 0; s < 2; s++) {
            unsigned ah[2][4], bh[4][2];
            int sc = (s << 1) | (q >> 1);
            int hb = (q & 1) << 3;
#pragma unroll
            for (int mt = 0; mt < 2; mt++) {
                int r0 = wm*32 + mt*16 + g;
                int off0 = r0 * 64 + ((sc ^ (r0 & 3)) << 4) + hb;
                uint2 v0 = *(const uint2*)(AhS + off0);
                uint2 v1 = *(const uint2*)(AhS + off0 + 512);
                ah[mt][0] = v0.x; ah[mt][1] = v1.x; ah[mt][2] = v0.y; ah[mt][3] = v1.y;
            }
#pragma unroll
            for (int nt = 0; nt < 4; nt++) {
                int n = wn*32 + nt*8 + g;
                int off = n * 64 + ((sc ^ (n & 3)) << 4) + hb;
                uint2 vb = *(const uint2*)(BhS + off);
                bh[nt][0] = vb.x; bh[nt][1] = vb.y;
            }
#pragma unroll
            for (int mt = 0; mt < 2; mt++)
#pragma unroll
                for (int nt = 0; nt < 4; nt++)
                    MMA_BF16(acc[mt][nt], ah[mt], bh[nt]);
        }
        if (kt + 2 < T) { stage(kt + 2, (kt + 2) % 3); CP_COMMIT(); }
    }
    unsigned char* M = g_simM + (size_t)img * NN * NN;
#pragma unroll
    for (int mt = 0; mt < 2; mt++)
#pragma unroll
        for (int nt = 0; nt < 4; nt++) {
            int s0 = m0 + wm*32 + mt*16 + g;
            int d0 = n0 + wn*32 + nt*8 + (q << 1);
            unsigned char v00 = (unsigned char)((acc[mt][nt][0] >= 0.4f) || (s0 == d0));
            unsigned char v01 = (unsigned char)((acc[mt][nt][1] >= 0.4f) || (s0 == d0+1));
            unsigned char v10 = (unsigned char)((acc[mt][nt][2] >= 0.4f) || (s0+8 == d0));
            unsigned char v11 = (unsigned char)((acc[mt][nt][3] >= 0.4f) || (s0+8 == d0+1));
            M[(size_t)d0 * NN + s0]       = v00;
            M[(size_t)(d0+1) * NN + s0]   = v01;
            M[(size_t)d0 * NN + s0+8]     = v10;
            M[(size_t)(d0+1) * NN + s0+8] = v11;
            M[(size_t)s0 * NN + d0]       = v00;
            M[(size_t)s0 * NN + d0+1]     = v01;
            M[(size_t)(s0+8) * NN + d0]   = v10;
            M[(size_t)(s0+8) * NN + d0+1] = v11;
        }
}

// FUSED GAT2 aggregation + node head + softmax: warp per dst.
__global__ void gat2_node_kernel(const float* __restrict__ b2,
                                 const float* __restrict__ nW,
                                 const float* __restrict__ nb,
                                 float* __restrict__ out) {
    __shared__ float sh_x[8][NC];
    int img = blockIdx.y, tid = threadIdx.x;
    int warp = tid >> 5, lane = tid & 31;
    int d = blockIdx.x * 8 + warp;
    int gd = img * NN + d;
    const unsigned char* M = g_simM + (size_t)img * NN * NN + (size_t)d * NN;
    float ed = g_ED2[gd];
    float shift = lrelu(fdec(g_M2[img]) + ed);
    float acc = 0.f, den = 0.f;
    for (int p = 0; p < 32; p++) {
        bool f = M[p * 32 + lane] != 0;
        unsigned bits = __ballot_sync(0xffffffffu, f);
        while (bits) {
            int b = __ffs(bits) - 1;
            bits &= bits - 1;
            int gs = (img << 10) + p * 32 + b;
            float w = __expf(lrelu(g_ES2[gs] + ed) - shift);
            den += w;
            if (lane < NC) acc = fmaf(w, g_H2[gs * NC + lane], acc);
        }
    }
    if (lane < NC) sh_x[warp][lane] = acc / den + b2[lane];
    __syncwarp();
    float a = -1e30f;
    if (lane < NC) {
        a = nb[lane];
#pragma unroll
        for (int cc = 0; cc < NC; cc++) a = fmaf(sh_x[warp][cc], nW[cc * NC + lane], a);
    }
    float m = a;
#pragma unroll
    for (int off = 16; off > 0; off >>= 1) m = fmaxf(m, __shfl_xor_sync(0xffffffffu, m, off));
    float e = (lane < NC) ? __expf(a - m) : 0.f;
    float s = e;
#pragma unroll
    for (int off = 16; off > 0; off >>= 1) s += __shfl_xor_sync(0xffffffffu, s, off);
    if (lane < NC) out[OUT_NODE + (size_t)gd * NC + lane] = e / s;
}

__global__ void graph_kernel(float* __restrict__ out) {
    int img = blockIdx.x, c = blockIdx.y, tid = threadIdx.x;  // 256 threads
    float s = 0.f;
    for (int node = tid; node < NN; node += 256)
        s += out[OUT_NODE + (size_t)(img * NN + node) * NC + c];
#pragma unroll
    for (int off = 16; off > 0; off >>= 1) s += __shfl_xor_sync(0xffffffffu, s, off);
    __shared__ float red[8];
    if ((tid & 31) == 0) red[tid >> 5] = s;
    __syncthreads();
    if (tid == 0) {
        float tot = 0.f;
#pragma unroll
        for (int i = 0; i < 8; i++) tot += red[i];
        out[img * NC + c] = tot * (1.f / (float)NN);
    }
}

// ---------------- launch ----------------
extern "C" void kernel_launch(void* const* d_in, const int* in_sizes, int n_in,
                              void* d_out, int out_size) {
    const float* x1     = (const float*)d_in[0];
    const float* boxes  = (const float*)d_in[1];
    const float* simW   = (const float*)d_in[2];
    const float* simb   = (const float*)d_in[3];
    const float* gat1W  = (const float*)d_in[4];
    const float* asrc1  = (const float*)d_in[5];
    const float* adst1  = (const float*)d_in[6];
    const float* b1     = (const float*)d_in[7];
    const float* gat2W  = (const float*)d_in[8];
    const float* asrc2  = (const float*)d_in[9];
    const float* adst2  = (const float*)d_in[10];
    const float* b2     = (const float*)d_in[11];
    const float* nodeW  = (const float*)d_in[12];
    const float* nodeb  = (const float*)d_in[13];
    const float* refW   = (const float*)d_in[14];
    const float* refb   = (const float*)d_in[15];
    const float* bboxW  = (const float*)d_in[16];
    const float* bboxb  = (const float*)d_in[17];
    float* out = (float*)d_out;

    cudaFuncSetAttribute(sgemm_tc_pipe,    cudaFuncAttributeMaxDynamicSharedMemorySize, SGEMM_SMEM);
    cudaFuncSetAttribute(gat1_gram_kernel, cudaFuncAttributeMaxDynamicSharedMemorySize, GRAM_SMEM);

    prep_kernel<<<PREP_GRID, 256>>>(x1, simW, gat1W, refW, bboxW, boxes);
    sgemm_tc_pipe<<<GRID_W, 256, SGEMM_SMEM>>>(out, refb, bboxb);
    norm_edge_kernel<<<NODES, 128>>>(simb, asrc1, adst1);
    gat1_gram_kernel<<<GG_GRID, 256, GRAM_SMEM>>>(b1, gat2W, asrc2, adst2);
    gat2_node_kernel<<<dim3(NN / 8, BI), 256>>>(b2, nodeW, nodeb, out);
    graph_kernel<<<dim3(BI, NC), 256>>>(out);
}